// round 3
// baseline (speedup 1.0000x reference)
#include <cuda_runtime.h>

#define BT 640
#define NWARP 20
#define RHO_F 1060.0f
#define CCFL_F 0.9f
#define EPS_AF 1e-6f
#define MAX_CTA 160
#define MAX_T 256

// Per-(step, cta) publication records — distinct addresses, no atomics.
// recR[t][c] = {maxbits, A_last, Q_last, FQ_last}    (ready: .x bits != 0)
// recL[t][c] = {A_first, Q_first, FQ_first, maxbits} (ready: .w bits != 0)
__device__ float4 g_recR[MAX_T][MAX_CTA];
__device__ float4 g_recL[MAX_T][MAX_CTA];

__device__ __forceinline__ float4 ld_acq_v4(const float4* p) {
    float4 v;
    asm volatile("ld.acquire.gpu.global.v4.f32 {%0,%1,%2,%3}, [%4];"
                 : "=f"(v.x), "=f"(v.y), "=f"(v.z), "=f"(v.w) : "l"(p) : "memory");
    return v;
}
__device__ __forceinline__ void st_rel_v4(float4* p, float4 v) {
    asm volatile("st.release.gpu.global.v4.f32 [%0], {%1,%2,%3,%4};"
                 :: "l"(p), "f"(v.x), "f"(v.y), "f"(v.z), "f"(v.w) : "memory");
}
__device__ __forceinline__ float sqrt_fast(float x) {
    float y; asm("sqrt.approx.f32 %0, %1;" : "=f"(y) : "f"(x)); return y;
}

__global__ void sim_init_kernel(int nrec) {
    int i = blockIdx.x * blockDim.x + threadIdx.x;
    float4 z = make_float4(0.f, 0.f, 0.f, 0.f);
    if (i < nrec) {
        ((float4*)g_recR)[i] = z;
        ((float4*)g_recL)[i] = z;
    }
}

__global__ void __launch_bounds__(BT, 1) sim_kernel(
    const float* __restrict__ Rs,
    const float* __restrict__ sim_dat,      // (2, M)
    const float* __restrict__ sdc,          // (11, M)
    const float* __restrict__ input_data,   // (T,)
    const int*   __restrict__ strides,      // (3, 2)
    float*       __restrict__ out,          // (T, 3)
    int M, int T)
{
    __shared__ float sA[2][BT], sQ[2][BT], sF[2][BT];
    __shared__ int   wmax[NWARP];
    __shared__ float bc[9];          // [0]=smax [1]=lam [2]=inflow [3..5]=left AQF [6..8]=right AQF
    __shared__ float sEF[3], sEL[3]; // this-CTA first/last point state
    __shared__ float sIn[256];       // input_data cache

    const int tid  = threadIdx.x;
    const int lane = tid & 31;
    const int wid  = tid >> 5;
    const int cta  = blockIdx.x;
    const int nCTA = gridDim.x;
    const int gi   = cta * BT + tid;
    const bool active = gi < M;

    for (int i = tid; i < T; i += BT) sIn[i] = input_data[i];
    if (tid >= 3 && tid < 9) bc[tid] = 1.0f;   // default edges (domain boundaries never use them)

    const int st0 = strides[0], st1 = strides[2], st2 = strides[4];
    const int en0 = strides[1] - 1, en1 = strides[3] - 1, en2 = strides[5] - 1;
    const int mid0 = (strides[0] + strides[1]) >> 1;
    const int mid1 = (strides[2] + strides[3]) >> 1;
    const int mid2 = (strides[4] + strides[5]) >> 1;

    const bool is_start = active && (gi == st0 || gi == st1 || gi == st2);
    const bool is_end   = active && (gi == en0 || gi == en1 || gi == en2);
    const bool interior = active && gi > 0 && gi < M - 1;
    const int  midv = (gi == mid0) ? 0 : (gi == mid1) ? 1 : (gi == mid2) ? 2 : -1;

    // per-point constants + initial state
    float A = 1.0f, Q = 0.0f, invA0 = 1.0f, beta = 1.0f, Rtot = 1.0f;
    if (active) {
        A = fmaxf(sim_dat[gi], EPS_AF);
        Q = 0.1f * sim_dat[M + gi];
        invA0 = __fdividef(1.0f, sdc[gi] + 0.5f);
        beta = sdc[M + gi] + 1.0f;
        if (is_end) {
            float R1 = sdc[7 * M + gi] + 0.5f;
            float R2 = sdc[8 * M + gi] + 0.5f;
            bool m1 = (gi >= strides[2]) && (gi < strides[3]);
            bool m2 = (gi >= strides[4]) && (gi < strides[5]);
            float rsv[4];
#pragma unroll
            for (int j = 0; j < 4; j++) {
                float x = Rs[j];
                rsv[j] = fmaxf(x, 0.0f) + log1pf(expf(-fabsf(x)));   // softplus
            }
            if (m1)      { R1 *= rsv[0]; R2 *= rsv[1]; }
            else if (m2) { R1 *= rsv[2]; R2 *= rsv[3]; }
            Rtot = R1 + R2;
        }
    }
    const float cc  = beta * (0.5f / RHO_F);
    const float fqc = beta * invA0 * (1.0f / (3.0f * RHO_F));

    // ---- prologue: state-0 derived quantities, publish rec[0] ----
    float sq = 1.0f, FQ = 0.0f, sval = 0.0f;
    if (active) {
        sq = sqrt_fast(A * invA0);
        float u = __fdividef(Q, A);
        float c = sqrt_fast(cc * sq);
        sval = fabsf(u) + c;
        FQ = Q * u + fqc * A * sq;
    }
    sA[0][tid] = A; sQ[0][tid] = Q; sF[0][tid] = FQ;
    if (tid == 0)      { sEF[0] = A; sEF[1] = Q; sEF[2] = FQ; }
    if (tid == BT - 1) { sEL[0] = A; sEL[1] = Q; sEL[2] = FQ; }
    {
        int wv = __reduce_max_sync(0xFFFFFFFFu, __float_as_int(sval));
        if (lane == 0) wmax[wid] = wv;
    }
    __syncthreads();
    if (wid == 0) {
        int v = __reduce_max_sync(0xFFFFFFFFu, (lane < NWARP) ? wmax[lane] : 0);
        if (lane == 0) {
            float mf = __int_as_float(v);
            st_rel_v4(&g_recL[0][cta], make_float4(sEF[0], sEF[1], sEF[2], mf));
            st_rel_v4(&g_recR[0][cta], make_float4(mf, sEL[0], sEL[1], sEL[2]));
        }
    }

    const bool haveL = tid > 0, haveR = tid < BT - 1;

    for (int t = 0; t < T; ++t) {
        const int b = t & 1, nb = b ^ 1;

        // ---- PRE-BARRIER: everything not needing smax ----
        // Factorization: lam*h = (CCFL/smax)*(0.5*smax) = 0.45 (constant!)
        //   A_new = [A + 0.45*(Ar-2A+Al)] - lam*0.5*(Qr-Ql)
        //   Q_new = [Q + 0.45*(Qr-2Q+Ql)] - lam*0.5*(Fr-Fl)
        float Al, Ql, Fl, Ar, Qr, Fr;
        float dA1 = 0.f, dQ1 = 0.f, cA = A, cQ = Q;
        if (haveL && haveR) {
            Al = sA[b][tid - 1]; Ql = sQ[b][tid - 1]; Fl = sF[b][tid - 1];
            Ar = sA[b][tid + 1]; Qr = sQ[b][tid + 1]; Fr = sF[b][tid + 1];
            dA1 = 0.5f * (Qr - Ql);
            dQ1 = 0.5f * (Fr - Fl);
            cA  = fmaf(0.45f, Ar - 2.0f * A + Al, A);
            cQ  = fmaf(0.45f, Qr - 2.0f * Q + Ql, Q);
        }
        const float P = beta * (sq - 1.0f);
        if (midv >= 0) out[t * 3 + midv] = P;
        const float Qend = is_end ? __fdividef(P, Rtot) : 0.0f;

        // ---- barrier: warp 0 polls all per-CTA step-t records ----
        if (wid == 0) {
            float4 r[5]; float4 rl;
            unsigned want = 0;
#pragma unroll
            for (int j = 0; j < 5; j++)
                if (lane + 32 * j < nCTA) want |= 1u << j;
            const bool needL = (lane == 31) && (cta + 1 < nCTA);
            if (needL) want |= 32u;
            unsigned done = 0;
            while (done != want) {
#pragma unroll
                for (int j = 0; j < 5; j++) {
                    if ((want & (1u << j)) && !(done & (1u << j))) {
                        r[j] = ld_acq_v4(&g_recR[t][lane + 32 * j]);
                        if (__float_as_int(r[j].x) != 0) done |= 1u << j;
                    }
                }
                if ((want & 32u) && !(done & 32u)) {
                    rl = ld_acq_v4(&g_recL[t][cta + 1]);
                    if (__float_as_int(rl.w) != 0) done |= 32u;
                }
            }
            int mb = 0;
#pragma unroll
            for (int j = 0; j < 5; j++)
                if (want & (1u << j)) mb = max(mb, __float_as_int(r[j].x));
            mb = __reduce_max_sync(0xFFFFFFFFu, mb);
            if (cta > 0) {
                int src = cta - 1;
                if (lane == (src & 31)) {
                    float4 rv = r[src >> 5];
                    bc[3] = rv.y; bc[4] = rv.z; bc[5] = rv.w;
                }
            }
            if (needL) { bc[6] = rl.x; bc[7] = rl.y; bc[8] = rl.z; }
            if (lane == 0) {
                float smax = __int_as_float(mb);
                bc[0] = smax;
                bc[1] = __fdividef(CCFL_F, smax);
                bc[2] = sIn[t];
            }
        }
        __syncthreads();
        const float lam = bc[1], inflow = bc[2];

        // edge threads compute their diffs now (neighbor data just arrived)
        if (!haveL || !haveR) {
            if (!haveL) { Al = bc[3]; Ql = bc[4]; Fl = bc[5]; }
            else        { Al = sA[b][tid - 1]; Ql = sQ[b][tid - 1]; Fl = sF[b][tid - 1]; }
            if (!haveR) { Ar = bc[6]; Qr = bc[7]; Fr = bc[8]; }
            else        { Ar = sA[b][tid + 1]; Qr = sQ[b][tid + 1]; Fr = sF[b][tid + 1]; }
            dA1 = 0.5f * (Qr - Ql);
            dQ1 = 0.5f * (Fr - Fl);
            cA  = fmaf(0.45f, Ar - 2.0f * A + Al, A);
            cQ  = fmaf(0.45f, Qr - 2.0f * Q + Ql, Q);
        }

        // ---- POST-BARRIER: 2 FMAs + derived-state chain ----
        float An = interior ? cA - lam * dA1 : A;
        float Qn = interior ? cQ - lam * dQ1 : Q;
        if (is_start) Qn = inflow;
        if (is_end)   Qn = Qend;
        An = fmaxf(An, EPS_AF);

        float snew = 0.0f;
        if (active) {
            A = An; Q = Qn;
            sq = sqrt_fast(A * invA0);
            float u = __fdividef(Q, A);
            float c = sqrt_fast(cc * sq);
            snew = fabsf(u) + c;
            FQ = fmaf(Q, u, fqc * A * sq);
        }

        sA[nb][tid] = A; sQ[nb][tid] = Q; sF[nb][tid] = FQ;
        if (tid == 0)      { sEF[0] = A; sEF[1] = Q; sEF[2] = FQ; }
        if (tid == BT - 1) { sEL[0] = A; sEL[1] = Q; sEL[2] = FQ; }
        int wv = __reduce_max_sync(0xFFFFFFFFu, __float_as_int(snew));
        if (lane == 0) wmax[wid] = wv;
        __syncthreads();
        if (wid == 0) {
            int v = __reduce_max_sync(0xFFFFFFFFu, (lane < NWARP) ? wmax[lane] : 0);
            if (lane == 0) {
                float mf = __int_as_float(v);
                st_rel_v4(&g_recL[t + 1][cta], make_float4(sEF[0], sEF[1], sEF[2], mf));
                st_rel_v4(&g_recR[t + 1][cta], make_float4(mf, sEL[0], sEL[1], sEL[2]));
            }
        }
    }
}

extern "C" void kernel_launch(void* const* d_in, const int* in_sizes, int n_in,
                              void* d_out, int out_size) {
    const float* Rs         = (const float*)d_in[0];
    const float* sim_dat    = (const float*)d_in[1];
    const float* sdc        = (const float*)d_in[2];
    const float* input_data = (const float*)d_in[3];
    const int*   strides    = (const int*)d_in[4];

    int M = in_sizes[1] / 2;     // sim_dat is (2, M)
    int T = in_sizes[3];         // input_data length

    int nCTA = (M + BT - 1) / BT;   // 141 for M=90000 — 1 CTA/SM, all co-resident

    int nrec = (T + 1) * MAX_CTA;
    sim_init_kernel<<<(nrec + 255) / 256, 256>>>(nrec);
    sim_kernel<<<nCTA, BT>>>(Rs, sim_dat, sdc, input_data, strides, (float*)d_out, M, T);
}

// round 4
// speedup vs baseline: 1.7900x; 1.7900x over previous
#include <cuda_runtime.h>

#define BT 640
#define NWARP 20
#define RHO_F 1060.0f
#define CCFL_F 0.9f
#define EPS_AF 1e-6f
#define MAX_CTA 160
#define MAX_T 256

// Persistent-kernel scratch.
__device__ unsigned g_smax_bits[MAX_T];     // per-step global max (float bits, positive)
__device__ unsigned g_count;                // grid barrier arrival counter
__device__ float4   g_edgeL[2][MAX_CTA];    // [buf][cta] first-point {A,Q,FQ,_}
__device__ float4   g_edgeR[2][MAX_CTA];    // [buf][cta] last-point  {A,Q,FQ,_}

__device__ __forceinline__ unsigned ld_acq_u32(const unsigned* p) {
    unsigned v;
    asm volatile("ld.global.acquire.gpu.u32 %0, [%1];" : "=r"(v) : "l"(p) : "memory");
    return v;
}
__device__ __forceinline__ float4 ld_acq_v4(const float4* p) {
    float4 v;
    asm volatile("ld.acquire.gpu.global.v4.f32 {%0,%1,%2,%3}, [%4];"
                 : "=f"(v.x), "=f"(v.y), "=f"(v.z), "=f"(v.w) : "l"(p) : "memory");
    return v;
}
__device__ __forceinline__ void red_max_relaxed(unsigned* p, unsigned v) {
    asm volatile("red.relaxed.gpu.global.max.u32 [%0], %1;" :: "l"(p), "r"(v) : "memory");
}
__device__ __forceinline__ void red_add_release(unsigned* p, unsigned v) {
    asm volatile("red.release.gpu.global.add.u32 [%0], %1;" :: "l"(p), "r"(v) : "memory");
}
__device__ __forceinline__ float sqrt_fast(float x) {
    float y; asm("sqrt.approx.f32 %0, %1;" : "=f"(y) : "f"(x)); return y;
}

__global__ void sim_init_kernel() {
    int i = blockIdx.x * blockDim.x + threadIdx.x;
    if (i < MAX_T) g_smax_bits[i] = 0u;
    if (i == 0) g_count = 0u;
}

__global__ void __launch_bounds__(BT, 1) sim_kernel(
    const float* __restrict__ Rs,
    const float* __restrict__ sim_dat,      // (2, M)
    const float* __restrict__ sdc,          // (11, M)
    const float* __restrict__ input_data,   // (T,)
    const int*   __restrict__ strides,      // (3, 2)
    float*       __restrict__ out,          // (T, 3)
    int M, int T)
{
    __shared__ float sA[2][BT], sQ[2][BT], sF[2][BT];
    __shared__ int   wmax[NWARP];
    __shared__ float bc[9];        // [0]=smax [1]=lam [2]=inflow [3..5]=leftAQF [6..8]=rightAQF
    __shared__ float sIn[256];

    const int tid  = threadIdx.x;
    const int lane = tid & 31;
    const int wid  = tid >> 5;
    const int cta  = blockIdx.x;
    const int nCTA = gridDim.x;
    const int gi   = cta * BT + tid;
    const bool active = gi < M;

    for (int i = tid; i < T; i += BT) sIn[i] = input_data[i];
    if (tid >= 3 && tid < 9) bc[tid] = 1.0f;

    const int st0 = strides[0], st1 = strides[2], st2 = strides[4];
    const int en0 = strides[1] - 1, en1 = strides[3] - 1, en2 = strides[5] - 1;
    const int mid0 = (strides[0] + strides[1]) >> 1;
    const int mid1 = (strides[2] + strides[3]) >> 1;
    const int mid2 = (strides[4] + strides[5]) >> 1;

    const bool is_start = active && (gi == st0 || gi == st1 || gi == st2);
    const bool is_end   = active && (gi == en0 || gi == en1 || gi == en2);
    const bool interior = active && gi > 0 && gi < M - 1;
    const int  midv = (gi == mid0) ? 0 : (gi == mid1) ? 1 : (gi == mid2) ? 2 : -1;

    float A = 1.0f, Q = 0.0f, invA0 = 1.0f, beta = 1.0f, Rtot = 1.0f;
    if (active) {
        A = fmaxf(sim_dat[gi], EPS_AF);
        Q = 0.1f * sim_dat[M + gi];
        invA0 = __fdividef(1.0f, sdc[gi] + 0.5f);
        beta = sdc[M + gi] + 1.0f;
        if (is_end) {
            float R1 = sdc[7 * M + gi] + 0.5f;
            float R2 = sdc[8 * M + gi] + 0.5f;
            bool m1 = (gi >= strides[2]) && (gi < strides[3]);
            bool m2 = (gi >= strides[4]) && (gi < strides[5]);
            float rsv[4];
#pragma unroll
            for (int j = 0; j < 4; j++) {
                float x = Rs[j];
                rsv[j] = fmaxf(x, 0.0f) + log1pf(expf(-fabsf(x)));   // softplus
            }
            if (m1)      { R1 *= rsv[0]; R2 *= rsv[1]; }
            else if (m2) { R1 *= rsv[2]; R2 *= rsv[3]; }
            Rtot = R1 + R2;
        }
    }
    const float cc  = beta * (0.5f / RHO_F);
    const float fqc = beta * invA0 * (1.0f / (3.0f * RHO_F));

    // ---- prologue: state-0 derived quantities, publish ----
    float sq = 1.0f, FQ = 0.0f, sval = 0.0f;
    if (active) {
        sq = sqrt_fast(A * invA0);
        float u = __fdividef(Q, A);
        float c = sqrt_fast(cc * sq);
        sval = fabsf(u) + c;
        FQ = Q * u + fqc * A * sq;
    }
    sA[0][tid] = A; sQ[0][tid] = Q; sF[0][tid] = FQ;
    if (tid == 0)      g_edgeL[0][cta] = make_float4(A, Q, FQ, 0.f);
    if (tid == BT - 1) g_edgeR[0][cta] = make_float4(A, Q, FQ, 0.f);
    {
        int wv = __reduce_max_sync(0xFFFFFFFFu, __float_as_int(sval));
        if (lane == 0) wmax[wid] = wv;
    }
    __syncthreads();
    if (wid == 0) {
        int v = __reduce_max_sync(0xFFFFFFFFu, (lane < NWARP) ? wmax[lane] : 0);
        if (lane == 0) {
            red_max_relaxed(&g_smax_bits[0], (unsigned)v);
            red_add_release(&g_count, 1u);
        }
    }

    const bool haveL = tid > 0, haveR = tid < BT - 1;

    for (int t = 0; t < T; ++t) {
        const int b = t & 1, nb = b ^ 1;

        // ---- PRE-BARRIER: everything not needing smax ----
        // lam*h = (CCFL/smax)*(0.5*smax) = 0.45 is constant:
        //   A_new = [A + 0.45*(Ar-2A+Al)] - lam*0.5*(Qr-Ql)
        //   Q_new = [Q + 0.45*(Qr-2Q+Ql)] - lam*0.5*(Fr-Fl)
        float Al, Ql, Fl, Ar, Qr, Fr;
        float dA1 = 0.f, dQ1 = 0.f, cA = A, cQ = Q;
        if (haveL && haveR) {
            Al = sA[b][tid - 1]; Ql = sQ[b][tid - 1]; Fl = sF[b][tid - 1];
            Ar = sA[b][tid + 1]; Qr = sQ[b][tid + 1]; Fr = sF[b][tid + 1];
            dA1 = 0.5f * (Qr - Ql);
            dQ1 = 0.5f * (Fr - Fl);
            cA  = fmaf(0.45f, Ar - 2.0f * A + Al, A);
            cQ  = fmaf(0.45f, Qr - 2.0f * Q + Ql, Q);
        }
        const float P = beta * (sq - 1.0f);
        if (midv >= 0) out[t * 3 + midv] = P;
        const float Qend = is_end ? __fdividef(P, Rtot) : 0.0f;

        // ---- grid barrier: tid0 spins on arrival count ----
        if (tid == 0) {
            const unsigned target = (unsigned)nCTA * (unsigned)(t + 1);
            while (ld_acq_u32(&g_count) < target) { }
            float smax = __int_as_float((int)ld_acq_u32(&g_smax_bits[t]));
            bc[0] = smax;
            bc[1] = __fdividef(CCFL_F, smax);
            bc[2] = sIn[t];
        }
        __syncthreads();
        const float lam = bc[1], inflow = bc[2];

        // edge threads: fetch cross-CTA halo (now safe) and build their terms
        if (!haveL || !haveR) {
            if (!haveL) {
                if (cta > 0) { float4 e = ld_acq_v4(&g_edgeR[b][cta - 1]); Al = e.x; Ql = e.y; Fl = e.z; }
                else         { Al = A; Ql = Q; Fl = FQ; }      // unused (gi==0 not interior)
            } else { Al = sA[b][tid - 1]; Ql = sQ[b][tid - 1]; Fl = sF[b][tid - 1]; }
            if (!haveR) {
                if (cta + 1 < nCTA) { float4 e = ld_acq_v4(&g_edgeL[b][cta + 1]); Ar = e.x; Qr = e.y; Fr = e.z; }
                else                { Ar = A; Qr = Q; Fr = FQ; } // unused (gi==M-1 not interior)
            } else { Ar = sA[b][tid + 1]; Qr = sQ[b][tid + 1]; Fr = sF[b][tid + 1]; }
            dA1 = 0.5f * (Qr - Ql);
            dQ1 = 0.5f * (Fr - Fl);
            cA  = fmaf(0.45f, Ar - 2.0f * A + Al, A);
            cQ  = fmaf(0.45f, Qr - 2.0f * Q + Ql, Q);
        }

        // ---- POST-BARRIER: short chain ----
        float An = interior ? cA - lam * dA1 : A;
        float Qn = interior ? cQ - lam * dQ1 : Q;
        if (is_start) Qn = inflow;
        if (is_end)   Qn = Qend;
        An = fmaxf(An, EPS_AF);

        float snew = 0.0f;
        if (active) {
            A = An; Q = Qn;
            sq = sqrt_fast(A * invA0);
            float u = __fdividef(Q, A);
            float c = sqrt_fast(cc * sq);
            snew = fabsf(u) + c;
            FQ = fmaf(Q, u, fqc * A * sq);
        }

        // publish new state BEFORE bar#2 (double-buffered; bar#2 orders vs next-iter reads)
        sA[nb][tid] = A; sQ[nb][tid] = Q; sF[nb][tid] = FQ;
        if (tid == 0)      g_edgeL[nb][cta] = make_float4(A, Q, FQ, 0.f);
        if (tid == BT - 1) g_edgeR[nb][cta] = make_float4(A, Q, FQ, 0.f);
        int wv = __reduce_max_sync(0xFFFFFFFFu, __float_as_int(snew));
        if (lane == 0) wmax[wid] = wv;
        __syncthreads();
        if (wid == 0) {
            int v = __reduce_max_sync(0xFFFFFFFFu, (lane < NWARP) ? wmax[lane] : 0);
            if (lane == 0) {
                red_max_relaxed(&g_smax_bits[t + 1], (unsigned)v);
                red_add_release(&g_count, 1u);   // release: covers edge/smem stores via bar.sync cumulativity
            }
        }
    }
}

extern "C" void kernel_launch(void* const* d_in, const int* in_sizes, int n_in,
                              void* d_out, int out_size) {
    const float* Rs         = (const float*)d_in[0];
    const float* sim_dat    = (const float*)d_in[1];
    const float* sdc        = (const float*)d_in[2];
    const float* input_data = (const float*)d_in[3];
    const int*   strides    = (const int*)d_in[4];

    int M = in_sizes[1] / 2;     // sim_dat is (2, M)
    int T = in_sizes[3];         // input_data length

    int nCTA = (M + BT - 1) / BT;   // 141 — 1 CTA/SM, all co-resident

    sim_init_kernel<<<(MAX_T + 255) / 256, 256>>>();
    sim_kernel<<<nCTA, BT>>>(Rs, sim_dat, sdc, input_data, strides, (float*)d_out, M, T);
}